// round 4
// baseline (speedup 1.0000x reference)
#include <cuda_runtime.h>
#include <cstdint>

#define B_   128
#define T_   512
#define DIM_ 256
#define E_   512
#define H_   512

// ---------------- device scratch ----------------
__device__ float g_xe[(size_t)B_ * T_ * E_];          // [m=b*T+t][e]
__device__ float g_gates[(size_t)T_ * B_ * 2048];     // [t][b][mcol], mcol = hcol*4+gate
__device__ float g_Wall[2048 * 512];                  // packed gate weights, row = mcol
__device__ float g_ball[2048];
__device__ float g_hP[2 * 16 * 64 * 32 * 2];          // [buf][bn][ks][lane][2] (tf32 bits)
__device__ unsigned g_flag[4 * 32];                   // per (ng, mg) monotonic progress flag

// ---------------- helpers ----------------
__device__ __forceinline__ unsigned tf32_(float f) {
    unsigned u;
    asm("cvt.rna.tf32.f32 %0, %1;" : "=r"(u) : "f"(f));
    return u;
}
__device__ __forceinline__ float tf32f_(float f) {
    return __uint_as_float(tf32_(f));
}

__device__ __forceinline__ void mma_tf32(float* d, const unsigned* a, unsigned b0, unsigned b1) {
    asm volatile(
        "mma.sync.aligned.m16n8k8.row.col.f32.tf32.tf32.f32 "
        "{%0,%1,%2,%3}, {%4,%5,%6,%7}, {%8,%9}, {%0,%1,%2,%3};"
        : "+f"(d[0]), "+f"(d[1]), "+f"(d[2]), "+f"(d[3])
        : "r"(a[0]), "r"(a[1]), "r"(a[2]), "r"(a[3]), "r"(b0), "r"(b1));
}

__device__ __forceinline__ float sigmoidf_(float x) {
    return 1.0f / (1.0f + __expf(-x));
}

__device__ __forceinline__ unsigned ld_relaxed(const unsigned* p) {
    unsigned v;
    asm volatile("ld.relaxed.gpu.global.b32 %0, [%1];" : "=r"(v) : "l"(p));
    return v;
}
__device__ __forceinline__ void st_relaxed(unsigned* p, unsigned v) {
    asm volatile("st.relaxed.gpu.global.b32 [%0], %1;" :: "l"(p), "r"(v));
}
__device__ __forceinline__ void fence_acqrel_gpu() {
    asm volatile("fence.acq_rel.gpu;" ::: "memory");
}

// ---------------- pack gate weights: row mcol = hcol*4+gate ----------------
__global__ void __launch_bounds__(256)
pack_w(const float* __restrict__ Wi, const float* __restrict__ Wf,
       const float* __restrict__ Wg, const float* __restrict__ Wo,
       const float* __restrict__ bi, const float* __restrict__ bf,
       const float* __restrict__ bg, const float* __restrict__ bo)
{
    const int idx = blockIdx.x * 256 + threadIdx.x;   // 2048*128 float4s
    const int n = idx >> 7, kq = idx & 127;
    const int gate = n & 3, hc = n >> 2;
    const float* W = (gate == 0) ? Wi : (gate == 1) ? Wf : (gate == 2) ? Wg : Wo;
    float4 v = *(const float4*)(W + (size_t)hc * 512 + kq * 4);
    *(float4*)(g_Wall + (size_t)n * 512 + kq * 4) = v;
    if (kq == 0) {
        const float* bb = (gate == 0) ? bi : (gate == 1) ? bf : (gate == 2) ? bg : bo;
        g_ball[n] = bb[hc];
    }
}

// ---------------- tf32 MMA GEMM: C = A @ W^T + bias ----------------
template <int KDIM, int MODE>
__global__ void __launch_bounds__(128)
gemm_tf32(const float* __restrict__ A_, const float* __restrict__ W_,
          const float* __restrict__ bias_)
{
    __shared__ float As[128 * 36];
    __shared__ float Ws[128 * 36];

    const float* A    = (MODE == 0) ? A_    : g_xe;
    const float* W    = (MODE == 0) ? W_    : g_Wall;
    const float* bias = (MODE == 0) ? bias_ : g_ball;

    const int tid = threadIdx.x, lane = tid & 31, warp = tid >> 5;
    const int wm = warp >> 1, wn = warp & 1;
    const int m0 = blockIdx.y * 128, n0 = blockIdx.x * 128;

    const int rb = tid >> 3;
    const int kq = tid & 7;
    const float* Ag = A + (size_t)(m0 + rb) * KDIM + kq * 4;
    const float* Wgp = W + (size_t)(n0 + rb) * KDIM + kq * 4;

    float4 pa[8], pw[8];
#pragma unroll
    for (int p = 0; p < 8; p++) {
        pa[p] = *(const float4*)(Ag  + (size_t)(16 * p) * KDIM);
        pw[p] = *(const float4*)(Wgp + (size_t)(16 * p) * KDIM);
    }

    float acc[4][8][4];
#pragma unroll
    for (int mt = 0; mt < 4; mt++)
#pragma unroll
        for (int nt = 0; nt < 8; nt++)
#pragma unroll
            for (int r = 0; r < 4; r++) acc[mt][nt][r] = 0.0f;

    const int g = lane >> 2, t = lane & 3;

    for (int kk = 0; kk < KDIM; kk += 32) {
#pragma unroll
        for (int p = 0; p < 8; p++) {
            const int ro = (rb + 16 * p) * 36 + kq * 4;
            float4 a = pa[p], w = pw[p];
            *(float4*)(As + ro) = make_float4(tf32f_(a.x), tf32f_(a.y), tf32f_(a.z), tf32f_(a.w));
            *(float4*)(Ws + ro) = make_float4(tf32f_(w.x), tf32f_(w.y), tf32f_(w.z), tf32f_(w.w));
        }
        __syncthreads();

        if (kk + 32 < KDIM) {
#pragma unroll
            for (int p = 0; p < 8; p++) {
                pa[p] = *(const float4*)(Ag  + (kk + 32) + (size_t)(16 * p) * KDIM);
                pw[p] = *(const float4*)(Wgp + (kk + 32) + (size_t)(16 * p) * KDIM);
            }
        }

#pragma unroll
        for (int s = 0; s < 4; s++) {
            unsigned af[4][4], bf[8][2];
#pragma unroll
            for (int mt = 0; mt < 4; mt++) {
                const int r = (wm * 64 + mt * 16 + g) * 36 + s * 8 + t;
                af[mt][0] = __float_as_uint(As[r]);
                af[mt][1] = __float_as_uint(As[r + 8 * 36]);
                af[mt][2] = __float_as_uint(As[r + 4]);
                af[mt][3] = __float_as_uint(As[r + 8 * 36 + 4]);
            }
#pragma unroll
            for (int nt = 0; nt < 8; nt++) {
                const int r = (wn * 64 + nt * 8 + g) * 36 + s * 8 + t;
                bf[nt][0] = __float_as_uint(Ws[r]);
                bf[nt][1] = __float_as_uint(Ws[r + 4]);
            }
#pragma unroll
            for (int mt = 0; mt < 4; mt++)
#pragma unroll
                for (int nt = 0; nt < 8; nt++)
                    mma_tf32(acc[mt][nt], af[mt], bf[nt][0], bf[nt][1]);
        }
        __syncthreads();
    }

#pragma unroll
    for (int mt = 0; mt < 4; mt++) {
        const int row0 = m0 + wm * 64 + mt * 16 + g;
#pragma unroll
        for (int nt = 0; nt < 8; nt++) {
            const int col = n0 + wn * 64 + nt * 8 + t * 2;
            const float2 bv = *(const float2*)(bias + col);
            float2 v0 = make_float2(acc[mt][nt][0] + bv.x, acc[mt][nt][1] + bv.y);
            float2 v1 = make_float2(acc[mt][nt][2] + bv.x, acc[mt][nt][3] + bv.y);
            if (MODE == 0) {
                *(float2*)(g_xe + (size_t)row0 * E_ + col) = v0;
                *(float2*)(g_xe + (size_t)(row0 + 8) * E_ + col) = v1;
            } else {
                const int b0v = row0 >> 9, t0v = row0 & 511;
                const int b1v = (row0 + 8) >> 9, t1v = (row0 + 8) & 511;
                *(float2*)(g_gates + ((size_t)t0v * B_ + b0v) * 2048 + col) = v0;
                *(float2*)(g_gates + ((size_t)t1v * B_ + b1v) * 2048 + col) = v1;
            }
        }
    }
}

// ---------------- persistent tf32-MMA recurrence (flag-based sync) ----------------
// Grid 128 = mg(32) x ng(4). Per block: M=64 gate-rows (16 hcols), N=32 batches,
// full K=512. Progress flags: one per block, monotonic. Per run each flag
// advances by exactly 513 (init publish + 512 steps), so the start value S is
// identical across a group at every graph replay.
__global__ void __launch_bounds__(256, 1)
lstm_rec(const float* __restrict__ h0, const float* __restrict__ c0,
         const float* __restrict__ Ri, const float* __restrict__ Rf,
         const float* __restrict__ Rg, const float* __restrict__ Ro,
         float* __restrict__ out)
{
    extern __shared__ float smem[];
    uint4* Ra   = (uint4*)smem;           // [4 mt][64 ks][32 lane] uint4 = 131072 B
    float* gbuf = smem + 32768;           // [64][33] gate pre-activations from x
    float* pbuf = gbuf + 64 * 33;         // [64][33] full pre-activations

    const int tid  = threadIdx.x;
    const int lane = tid & 31;
    const int w    = tid >> 5;
    const int wm   = w >> 1;
    const int wn   = w & 1;
    const int gid  = lane >> 2;
    const int tig  = lane & 3;

    const int mg = blockIdx.x & 31;
    const int ng = blockIdx.x >> 5;
    const int M0 = mg * 64;
    const int hcol0 = mg * 16;
    const int batch0 = ng * 32;

    unsigned* myflag = &g_flag[ng * 32 + mg];
    const unsigned* grpflags = &g_flag[ng * 32];
    const unsigned S = ld_relaxed(myflag);   // self-owned: race-free

    // ---- arrange R into A-fragment order (one-time) ----
    const float* Rp0 = Ri; const float* Rp1 = Rf;
    const float* Rp2 = Rg; const float* Rp3 = Ro;
#pragma unroll 1
    for (int i = 0; i < 32; i++) {
        const int idx = tid + i * 256;
        const int mt = idx >> 11, ks = (idx >> 5) & 63, ln = idx & 31;
        const int g2 = ln >> 2, t2 = ln & 3;
        const int r0 = M0 + mt * 16 + g2, r1 = r0 + 8;
        const int k0 = ks * 8 + t2;
        const float* P0 = ((r0 & 3) == 0) ? Rp0 : ((r0 & 3) == 1) ? Rp1 : ((r0 & 3) == 2) ? Rp2 : Rp3;
        const float* P1 = ((r1 & 3) == 0) ? Rp0 : ((r1 & 3) == 1) ? Rp1 : ((r1 & 3) == 2) ? Rp2 : Rp3;
        const size_t o0 = (size_t)(r0 >> 2) * H_;
        const size_t o1 = (size_t)(r1 >> 2) * H_;
        uint4 v;
        v.x = tf32_(P0[o0 + k0]);
        v.y = tf32_(P1[o1 + k0]);
        v.z = tf32_(P0[o0 + k0 + 4]);
        v.w = tf32_(P1[o1 + k0 + 4]);
        Ra[idx] = v;
    }

    // ---- init c state + hP buffer 0 ----
    const int bl  = tid >> 3;
    const int hl0 = (tid & 7) * 2;
    float creg[2];
#pragma unroll
    for (int q = 0; q < 2; q++) {
        const int j = hcol0 + hl0 + q;
        const int b = batch0 + bl;
        creg[q] = c0[(size_t)b * H_ + j];
        const float hv = h0[(size_t)b * H_ + j];
        const size_t hidx = (((size_t)(b >> 3) * 64 + (j >> 3)) * 32 + ((b & 7) * 4 + (j & 3))) * 2 + ((j >> 2) & 1);
        g_hP[hidx] = __uint_as_float(tf32_(hv));
    }
    __threadfence();
    __syncthreads();
    if (tid == 0) st_relaxed(myflag, S + 1);   // publish h[0]

    const uint4* RaW = Ra + wm * 64 * 32;
    const int bnA = ng * 4 + wn * 2;
    const size_t BTH = (size_t)B_ * T_ * H_;
    const int r0r = wm * 16 + gid;

    for (int t = 0; t < T_; t++) {
        __syncthreads();   // hP[t] writes of iter t-1 done blockwide; pbuf reads done
        if (t > 0 && tid == 0) st_relaxed(myflag, S + 1 + (unsigned)t);  // publish h[t]

        // ---- gate prefetch: 8 consecutive mcols/thread -> gbuf ----
        {
            const int gbl = tid >> 3;
            const int ml  = (tid & 7) * 8;
            const float* gp = g_gates + ((size_t)t * B_ + (batch0 + gbl)) * 2048 + M0 + ml;
            float4 u0 = *(const float4*)gp;
            float4 u1 = *(const float4*)(gp + 4);
            gbuf[(ml + 0) * 33 + gbl] = u0.x;
            gbuf[(ml + 1) * 33 + gbl] = u0.y;
            gbuf[(ml + 2) * 33 + gbl] = u0.z;
            gbuf[(ml + 3) * 33 + gbl] = u0.w;
            gbuf[(ml + 4) * 33 + gbl] = u1.x;
            gbuf[(ml + 5) * 33 + gbl] = u1.y;
            gbuf[(ml + 6) * 33 + gbl] = u1.z;
            gbuf[(ml + 7) * 33 + gbl] = u1.w;
        }

        // ---- warp-parallel flag poll: lane l watches producer l ----
        {
            const unsigned target = S + 1 + (unsigned)t;
            unsigned f = ld_relaxed(grpflags + lane);
            unsigned ready = __ballot_sync(0xffffffffu, (int)(f - target) >= 0);
            while (ready != 0xffffffffu) {
                if (!((ready >> lane) & 1u)) f = ld_relaxed(grpflags + lane);
                ready = __ballot_sync(0xffffffffu, (int)(f - target) >= 0);
            }
            fence_acqrel_gpu();   // order subsequent hP loads after flag observation
        }

        // ---- MMA: acc[j] = (R @ h^T) tile ----
        float acc[2][4];
#pragma unroll
        for (int j = 0; j < 2; j++)
#pragma unroll
            for (int r = 0; r < 4; r++) acc[j][r] = 0.0f;

        const float2* hp = (const float2*)g_hP + (size_t)(t & 1) * (16 * 64 * 32);
#pragma unroll 8
        for (int ks = 0; ks < 64; ks++) {
            uint4 a = RaW[ks * 32 + lane];
            float2 bf0 = __ldcg(&hp[((size_t)bnA * 64 + ks) * 32 + lane]);
            float2 bf1 = __ldcg(&hp[((size_t)(bnA + 1) * 64 + ks) * 32 + lane]);
            mma_tf32(acc[0], (const unsigned*)&a, __float_as_uint(bf0.x), __float_as_uint(bf0.y));
            mma_tf32(acc[1], (const unsigned*)&a, __float_as_uint(bf1.x), __float_as_uint(bf1.y));
        }

        __syncthreads();   // gbuf ready

        // ---- add x-gate pre-activations, write full preacts to pbuf ----
#pragma unroll
        for (int j = 0; j < 2; j++) {
            const int cn = (wn * 2 + j) * 8 + tig * 2;
            pbuf[r0r * 33 + cn]           = acc[j][0] + gbuf[r0r * 33 + cn];
            pbuf[r0r * 33 + cn + 1]       = acc[j][1] + gbuf[r0r * 33 + cn + 1];
            pbuf[(r0r + 8) * 33 + cn]     = acc[j][2] + gbuf[(r0r + 8) * 33 + cn];
            pbuf[(r0r + 8) * 33 + cn + 1] = acc[j][3] + gbuf[(r0r + 8) * 33 + cn + 1];
        }
        __syncthreads();   // pbuf ready

        // ---- LSTM cell update ----
#pragma unroll
        for (int q = 0; q < 2; q++) {
            const int hl = hl0 + q;
            const int j  = hcol0 + hl;
            const int b  = batch0 + bl;
            const float pi = pbuf[(hl * 4 + 0) * 33 + bl];
            const float pf = pbuf[(hl * 4 + 1) * 33 + bl];
            const float pg = pbuf[(hl * 4 + 2) * 33 + bl];
            const float po = pbuf[(hl * 4 + 3) * 33 + bl];
            const float ig = sigmoidf_(pi);
            const float fg = sigmoidf_(pf);
            const float gg = tanhf(pg);
            const float og = sigmoidf_(po);
            const float cn2 = gg * ig + fg * creg[q];
            creg[q] = cn2;
            const float hn = og * tanhf(cn2);

            out[(size_t)b * (T_ * H_) + (size_t)t * H_ + j] = hn;
            const size_t hidx = ((size_t)((t + 1) & 1) * 16 * 64 * 32
                                 + ((size_t)(b >> 3) * 64 + (j >> 3)) * 32
                                 + ((b & 7) * 4 + (j & 3))) * 2 + ((j >> 2) & 1);
            g_hP[hidx] = __uint_as_float(tf32_(hn));
            if (t == T_ - 1) {
                out[BTH + (size_t)b * H_ + j] = hn;
                out[BTH + (size_t)(B_ * H_) + (size_t)b * H_ + j] = cn2;
            }
        }
        __threadfence();   // order hP[t+1] stores before the next flag publish
    }

    // final publish so every flag advances by exactly 513 per run
    __syncthreads();
    if (tid == 0) st_relaxed(myflag, S + 513);
}

// ---------------- launch ----------------
extern "C" void kernel_launch(void* const* d_in, const int* in_sizes, int n_in,
                              void* d_out, int out_size)
{
    (void)in_sizes; (void)n_in; (void)out_size;
    const float* x  = (const float*)d_in[0];
    const float* h0 = (const float*)d_in[1];
    const float* c0 = (const float*)d_in[2];
    const float* We = (const float*)d_in[3];
    const float* be = (const float*)d_in[4];
    const float* Wf = (const float*)d_in[5];
    const float* bf = (const float*)d_in[6];
    const float* Wi = (const float*)d_in[7];
    const float* bi = (const float*)d_in[8];
    const float* Wg = (const float*)d_in[9];
    const float* bg = (const float*)d_in[10];
    const float* Wo = (const float*)d_in[11];
    const float* bo = (const float*)d_in[12];
    const float* Rf = (const float*)d_in[13];
    const float* Ri = (const float*)d_in[14];
    const float* Rg = (const float*)d_in[15];
    const float* Ro = (const float*)d_in[16];
    float* out = (float*)d_out;

    static bool attr_set = false;
    if (!attr_set) {
        cudaFuncSetAttribute(lstm_rec,
                             cudaFuncAttributeMaxDynamicSharedMemorySize, 150000);
        attr_set = true;
    }

    // pack gate weights (i,f,g,o interleaved by mcol)
    pack_w<<<1024, 256>>>(Wi, Wf, Wg, Wo, bi, bf, bg, bo);

    // xe = x @ We^T + be  (tf32 MMA)
    gemm_tf32<DIM_, 0><<<dim3(E_ / 128, (B_ * T_) / 128), 128>>>(x, We, be);

    // gates = xe @ Wall^T + ball  (tf32 MMA, N=2048)
    gemm_tf32<E_, 1><<<dim3(2048 / 128, (B_ * T_) / 128), 128>>>(nullptr, nullptr, nullptr);

    // persistent tf32 recurrence (flag-synced)
    const int dynsmem = (32768 + 2 * 64 * 33) * 4;   // Ra + gbuf + pbuf = 147968 B
    lstm_rec<<<128, 256, dynsmem>>>(h0, c0, Ri, Rf, Rg, Ro, out);
}

// round 5
// speedup vs baseline: 2.5682x; 2.5682x over previous
#include <cuda_runtime.h>
#include <cstdint>

#define B_   128
#define T_   512
#define DIM_ 256
#define E_   512
#define H_   512

// ---------------- device scratch ----------------
__device__ float g_xe[(size_t)B_ * T_ * E_];          // [m=b*T+t][e]
__device__ float g_gates[(size_t)T_ * B_ * 2048];     // [t][b][mcol], mcol = hcol*4+gate
__device__ float g_Wall[2048 * 512];                  // packed gate weights, row = mcol
__device__ float g_ball[2048];
__device__ float g_hP[2 * 16 * 64 * 32 * 2];          // [buf][bn][ks][lane][2] (tf32 bits)
__device__ unsigned g_cnt2[4];
__device__ volatile unsigned g_gen2[4];

// ---------------- helpers ----------------
__device__ __forceinline__ unsigned tf32_(float f) {
    unsigned u;
    asm("cvt.rna.tf32.f32 %0, %1;" : "=r"(u) : "f"(f));
    return u;
}
__device__ __forceinline__ float tf32f_(float f) {
    return __uint_as_float(tf32_(f));
}

__device__ __forceinline__ void mma_tf32(float* d, const unsigned* a, unsigned b0, unsigned b1) {
    asm volatile(
        "mma.sync.aligned.m16n8k8.row.col.f32.tf32.tf32.f32 "
        "{%0,%1,%2,%3}, {%4,%5,%6,%7}, {%8,%9}, {%0,%1,%2,%3};"
        : "+f"(d[0]), "+f"(d[1]), "+f"(d[2]), "+f"(d[3])
        : "r"(a[0]), "r"(a[1]), "r"(a[2]), "r"(a[3]), "r"(b0), "r"(b1));
}

__device__ __forceinline__ float sigmoidf_(float x) {
    return 1.0f / (1.0f + __expf(-x));
}

// ---------------- pack gate weights: row mcol = hcol*4+gate ----------------
__global__ void __launch_bounds__(256)
pack_w(const float* __restrict__ Wi, const float* __restrict__ Wf,
       const float* __restrict__ Wg, const float* __restrict__ Wo,
       const float* __restrict__ bi, const float* __restrict__ bf,
       const float* __restrict__ bg, const float* __restrict__ bo)
{
    const int idx = blockIdx.x * 256 + threadIdx.x;   // 2048*128 float4s
    const int n = idx >> 7, kq = idx & 127;
    const int gate = n & 3, hc = n >> 2;
    const float* W = (gate == 0) ? Wi : (gate == 1) ? Wf : (gate == 2) ? Wg : Wo;
    float4 v = *(const float4*)(W + (size_t)hc * 512 + kq * 4);
    *(float4*)(g_Wall + (size_t)n * 512 + kq * 4) = v;
    if (kq == 0) {
        const float* bb = (gate == 0) ? bi : (gate == 1) ? bf : (gate == 2) ? bg : bo;
        g_ball[n] = bb[hc];
    }
}

// ---------------- tf32 MMA GEMM: C = A @ W^T + bias ----------------
template <int KDIM, int MODE>
__global__ void __launch_bounds__(128)
gemm_tf32(const float* __restrict__ A_, const float* __restrict__ W_,
          const float* __restrict__ bias_)
{
    __shared__ float As[128 * 36];
    __shared__ float Ws[128 * 36];

    const float* A    = (MODE == 0) ? A_    : g_xe;
    const float* W    = (MODE == 0) ? W_    : g_Wall;
    const float* bias = (MODE == 0) ? bias_ : g_ball;

    const int tid = threadIdx.x, lane = tid & 31, warp = tid >> 5;
    const int wm = warp >> 1, wn = warp & 1;
    const int m0 = blockIdx.y * 128, n0 = blockIdx.x * 128;

    const int rb = tid >> 3;
    const int kq = tid & 7;
    const float* Ag = A + (size_t)(m0 + rb) * KDIM + kq * 4;
    const float* Wgp = W + (size_t)(n0 + rb) * KDIM + kq * 4;

    float4 pa[8], pw[8];
#pragma unroll
    for (int p = 0; p < 8; p++) {
        pa[p] = *(const float4*)(Ag  + (size_t)(16 * p) * KDIM);
        pw[p] = *(const float4*)(Wgp + (size_t)(16 * p) * KDIM);
    }

    float acc[4][8][4];
#pragma unroll
    for (int mt = 0; mt < 4; mt++)
#pragma unroll
        for (int nt = 0; nt < 8; nt++)
#pragma unroll
            for (int r = 0; r < 4; r++) acc[mt][nt][r] = 0.0f;

    const int g = lane >> 2, t = lane & 3;

    for (int kk = 0; kk < KDIM; kk += 32) {
#pragma unroll
        for (int p = 0; p < 8; p++) {
            const int ro = (rb + 16 * p) * 36 + kq * 4;
            float4 a = pa[p], w = pw[p];
            *(float4*)(As + ro) = make_float4(tf32f_(a.x), tf32f_(a.y), tf32f_(a.z), tf32f_(a.w));
            *(float4*)(Ws + ro) = make_float4(tf32f_(w.x), tf32f_(w.y), tf32f_(w.z), tf32f_(w.w));
        }
        __syncthreads();

        if (kk + 32 < KDIM) {
#pragma unroll
            for (int p = 0; p < 8; p++) {
                pa[p] = *(const float4*)(Ag  + (kk + 32) + (size_t)(16 * p) * KDIM);
                pw[p] = *(const float4*)(Wgp + (kk + 32) + (size_t)(16 * p) * KDIM);
            }
        }

#pragma unroll
        for (int s = 0; s < 4; s++) {
            unsigned af[4][4], bf[8][2];
#pragma unroll
            for (int mt = 0; mt < 4; mt++) {
                const int r = (wm * 64 + mt * 16 + g) * 36 + s * 8 + t;
                af[mt][0] = __float_as_uint(As[r]);
                af[mt][1] = __float_as_uint(As[r + 8 * 36]);
                af[mt][2] = __float_as_uint(As[r + 4]);
                af[mt][3] = __float_as_uint(As[r + 8 * 36 + 4]);
            }
#pragma unroll
            for (int nt = 0; nt < 8; nt++) {
                const int r = (wn * 64 + nt * 8 + g) * 36 + s * 8 + t;
                bf[nt][0] = __float_as_uint(Ws[r]);
                bf[nt][1] = __float_as_uint(Ws[r + 4]);
            }
#pragma unroll
            for (int mt = 0; mt < 4; mt++)
#pragma unroll
                for (int nt = 0; nt < 8; nt++)
                    mma_tf32(acc[mt][nt], af[mt], bf[nt][0], bf[nt][1]);
        }
        __syncthreads();
    }

#pragma unroll
    for (int mt = 0; mt < 4; mt++) {
        const int row0 = m0 + wm * 64 + mt * 16 + g;
#pragma unroll
        for (int nt = 0; nt < 8; nt++) {
            const int col = n0 + wn * 64 + nt * 8 + t * 2;
            const float2 bv = *(const float2*)(bias + col);
            float2 v0 = make_float2(acc[mt][nt][0] + bv.x, acc[mt][nt][1] + bv.y);
            float2 v1 = make_float2(acc[mt][nt][2] + bv.x, acc[mt][nt][3] + bv.y);
            if (MODE == 0) {
                *(float2*)(g_xe + (size_t)row0 * E_ + col) = v0;
                *(float2*)(g_xe + (size_t)(row0 + 8) * E_ + col) = v1;
            } else {
                const int b0v = row0 >> 9, t0v = row0 & 511;
                const int b1v = (row0 + 8) >> 9, t1v = (row0 + 8) & 511;
                *(float2*)(g_gates + ((size_t)t0v * B_ + b0v) * 2048 + col) = v0;
                *(float2*)(g_gates + ((size_t)t1v * B_ + b1v) * 2048 + col) = v1;
            }
        }
    }
}

// ---------------- group barrier (32 blocks per batch-group, R3-proven) -------
__device__ __forceinline__ void group_barrier32(int ng) {
    __threadfence();
    __syncthreads();
    if (threadIdx.x == 0) {
        unsigned g = g_gen2[ng];
        unsigned old = atomicAdd(&g_cnt2[ng], 1u);
        if (old == 31u) {
            g_cnt2[ng] = 0u;
            __threadfence();
            g_gen2[ng] = g + 1u;
        } else {
            while (g_gen2[ng] == g) __nanosleep(20);
        }
        __threadfence();
    }
    __syncthreads();
}

// ---------------- persistent tf32-MMA recurrence ----------------
// Grid 128 = mg(32) x ng(4). Per block: M=64 gate-rows (16 hcols), N=32 batches,
// K=512. 8 warps = wm(2, m32 half) x wk(4, K quarter), each mt=2 x nt=4.
// h tile staged to smem once per step; K-partials summed via smem pbuf.
__global__ void __launch_bounds__(256, 1)
lstm_rec(const float* __restrict__ h0, const float* __restrict__ c0,
         const float* __restrict__ Ri, const float* __restrict__ Rf,
         const float* __restrict__ Rg, const float* __restrict__ Ro,
         float* __restrict__ out)
{
    extern __shared__ float smem[];
    uint4* Ra   = (uint4*)smem;            // [4 mt][64 ks][32 lane] uint4 = 131072 B
    float* hS   = smem + 32768;            // 16384 floats = 64 KB  (h tile, hP layout)
    float* pbuf = hS + 16384;              // [4 wk][64 row][33] = 33792 B

    const int tid  = threadIdx.x;
    const int lane = tid & 31;
    const int w    = tid >> 5;
    const int wm   = w >> 2;               // m32 half (0..1)
    const int wk   = w & 3;                // K quarter (0..3)
    const int gid  = lane >> 2;
    const int tig  = lane & 3;

    const int mg = blockIdx.x & 31;
    const int ng = blockIdx.x >> 5;
    const int M0 = mg * 64;
    const int hcol0 = mg * 16;
    const int batch0 = ng * 32;

    // ---- arrange R into A-fragment order (one-time) ----
    const float* Rp0 = Ri; const float* Rp1 = Rf;
    const float* Rp2 = Rg; const float* Rp3 = Ro;
#pragma unroll 1
    for (int i = 0; i < 32; i++) {
        const int idx = tid + i * 256;
        const int mt = idx >> 11, ks = (idx >> 5) & 63, ln = idx & 31;
        const int g2 = ln >> 2, t2 = ln & 3;
        const int r0 = M0 + mt * 16 + g2, r1 = r0 + 8;
        const int k0 = ks * 8 + t2;
        const float* P0 = ((r0 & 3) == 0) ? Rp0 : ((r0 & 3) == 1) ? Rp1 : ((r0 & 3) == 2) ? Rp2 : Rp3;
        const float* P1 = ((r1 & 3) == 0) ? Rp0 : ((r1 & 3) == 1) ? Rp1 : ((r1 & 3) == 2) ? Rp2 : Rp3;
        const size_t o0 = (size_t)(r0 >> 2) * H_;
        const size_t o1 = (size_t)(r1 >> 2) * H_;
        uint4 v;
        v.x = tf32_(P0[o0 + k0]);
        v.y = tf32_(P1[o1 + k0]);
        v.z = tf32_(P0[o0 + k0 + 4]);
        v.w = tf32_(P1[o1 + k0 + 4]);
        Ra[idx] = v;
    }

    // ---- init c state + hP buffer 0 ----
    const int bl  = tid >> 3;              // local batch (0..31)
    const int hl0 = (tid & 7) * 2;         // local hcol pair base
    float creg[2];
#pragma unroll
    for (int q = 0; q < 2; q++) {
        const int j = hcol0 + hl0 + q;
        const int b = batch0 + bl;
        creg[q] = c0[(size_t)b * H_ + j];
        const float hv = h0[(size_t)b * H_ + j];
        const size_t hidx = (((size_t)(b >> 3) * 64 + (j >> 3)) * 32 + ((b & 7) * 4 + (j & 3))) * 2 + ((j >> 2) & 1);
        g_hP[hidx] = __uint_as_float(tf32_(hv));
    }
    // h[0] is published by the loop-top barrier at t=0.

    const uint4* Ra0 = Ra + (2 * wm) * 2048;
    const uint4* Ra1 = Ra + (2 * wm + 1) * 2048;
    const float2* hS2 = (const float2*)hS;
    float* pb = pbuf + wk * 2112;
    const size_t BTH = (size_t)B_ * T_ * H_;
    const int ksbase = wk * 16;

    for (int t = 0; t < T_; t++) {
        // ---- gate prefetch into registers (L2/DRAM latency hidden by barrier) ----
        const float* gp = g_gates + ((size_t)t * B_ + (batch0 + bl)) * 2048 + M0 + (tid & 7) * 8;
        const float4 u0 = __ldg((const float4*)gp);
        const float4 u1 = __ldg((const float4*)(gp + 4));

        group_barrier32(ng);               // h[t] published by all producers

        // ---- stage h tile (64 KB) into smem ----
        {
            const float4* src4 = (const float4*)g_hP + (size_t)(t & 1) * 16384 + ng * 4096;
            float4* dst4 = (float4*)hS;
#pragma unroll
            for (int i = 0; i < 16; i++)
                dst4[tid + i * 256] = __ldcg(src4 + tid + i * 256);
        }
        __syncthreads();

        // ---- MMA: warp (wm, wk) computes mt=2 x nt=4 over its K quarter ----
        float acc[2][4][4];
#pragma unroll
        for (int i = 0; i < 2; i++)
#pragma unroll
            for (int j = 0; j < 4; j++)
#pragma unroll
                for (int r = 0; r < 4; r++) acc[i][j][r] = 0.0f;

#pragma unroll 4
        for (int ks16 = 0; ks16 < 16; ks16++) {
            const int ks = ksbase + ks16;
            uint4 a0 = Ra0[ks * 32 + lane];
            uint4 a1 = Ra1[ks * 32 + lane];
#pragma unroll
            for (int j = 0; j < 4; j++) {
                float2 b = hS2[(j * 64 + ks) * 32 + lane];
                const unsigned bx = __float_as_uint(b.x), by = __float_as_uint(b.y);
                mma_tf32(acc[0][j], (const unsigned*)&a0, bx, by);
                mma_tf32(acc[1][j], (const unsigned*)&a1, bx, by);
            }
        }

        // ---- store K-partials to pbuf[wk] ----
#pragma unroll
        for (int i = 0; i < 2; i++) {
            const int r = wm * 32 + i * 16 + gid;
#pragma unroll
            for (int j = 0; j < 4; j++) {
                const int c = j * 8 + tig * 2;
                pb[r * 33 + c]           = acc[i][j][0];
                pb[r * 33 + c + 1]       = acc[i][j][1];
                pb[(r + 8) * 33 + c]     = acc[i][j][2];
                pb[(r + 8) * 33 + c + 1] = acc[i][j][3];
            }
        }
        __syncthreads();

        // ---- LSTM cell update: sum 4 K-partials + gate regs ----
#pragma unroll
        for (int q = 0; q < 2; q++) {
            const int hl = hl0 + q;
            const int j  = hcol0 + hl;
            const int b  = batch0 + bl;
            float p[4];
#pragma unroll
            for (int gte = 0; gte < 4; gte++) {
                const int ro = (hl * 4 + gte) * 33 + bl;
                p[gte] = pbuf[ro] + pbuf[2112 + ro] + pbuf[2 * 2112 + ro] + pbuf[3 * 2112 + ro];
            }
            const float4 u = (q == 0) ? u0 : u1;
            const float ig = sigmoidf_(p[0] + u.x);
            const float fg = sigmoidf_(p[1] + u.y);
            const float gg = tanhf(p[2] + u.z);
            const float og = sigmoidf_(p[3] + u.w);
            const float cn2 = gg * ig + fg * creg[q];
            creg[q] = cn2;
            const float hn = og * tanhf(cn2);

            out[(size_t)b * (T_ * H_) + (size_t)t * H_ + j] = hn;
            const size_t hidx = ((size_t)((t + 1) & 1) * 16 * 64 * 32
                                 + ((size_t)(b >> 3) * 64 + (j >> 3)) * 32
                                 + ((b & 7) * 4 + (j & 3))) * 2 + ((j >> 2) & 1);
            g_hP[hidx] = __uint_as_float(tf32_(hn));
            if (t == T_ - 1) {
                out[BTH + (size_t)b * H_ + j] = hn;
                out[BTH + (size_t)(B_ * H_) + (size_t)b * H_ + j] = cn2;
            }
        }
        // next loop-top barrier publishes h[t+1] (threadfence inside)
    }
}

// ---------------- launch ----------------
extern "C" void kernel_launch(void* const* d_in, const int* in_sizes, int n_in,
                              void* d_out, int out_size)
{
    (void)in_sizes; (void)n_in; (void)out_size;
    const float* x  = (const float*)d_in[0];
    const float* h0 = (const float*)d_in[1];
    const float* c0 = (const float*)d_in[2];
    const float* We = (const float*)d_in[3];
    const float* be = (const float*)d_in[4];
    const float* Wf = (const float*)d_in[5];
    const float* bf = (const float*)d_in[6];
    const float* Wi = (const float*)d_in[7];
    const float* bi = (const float*)d_in[8];
    const float* Wg = (const float*)d_in[9];
    const float* bg = (const float*)d_in[10];
    const float* Wo = (const float*)d_in[11];
    const float* bo = (const float*)d_in[12];
    const float* Rf = (const float*)d_in[13];
    const float* Ri = (const float*)d_in[14];
    const float* Rg = (const float*)d_in[15];
    const float* Ro = (const float*)d_in[16];
    float* out = (float*)d_out;

    static bool attr_set = false;
    if (!attr_set) {
        cudaFuncSetAttribute(lstm_rec,
                             cudaFuncAttributeMaxDynamicSharedMemorySize, 230400);
        attr_set = true;
    }

    // pack gate weights (i,f,g,o interleaved by mcol)
    pack_w<<<1024, 256>>>(Wi, Wf, Wg, Wo, bi, bf, bg, bo);

    // xe = x @ We^T + be  (tf32 MMA)
    gemm_tf32<DIM_, 0><<<dim3(E_ / 128, (B_ * T_) / 128), 128>>>(x, We, be);

    // gates = xe @ Wall^T + ball  (tf32 MMA, N=2048)
    gemm_tf32<E_, 1><<<dim3(2048 / 128, (B_ * T_) / 128), 128>>>(nullptr, nullptr, nullptr);

    // persistent tf32 recurrence (counting-barrier sync, smem-staged h)
    const int dynsmem = 230400;   // Ra 128K + hS 64K + pbuf 33K
    lstm_rec<<<128, 256, dynsmem>>>(h0, c0, Ri, Rf, Rg, Ro, out);
}